// round 2
// baseline (speedup 1.0000x reference)
#include <cuda_runtime.h>
#include <cuda_bf16.h>
#include <cstdint>

// Problem constants
#define F_FIELDS 32
#define VOCAB    10000
#define D_EMB    496          // = 124 float4
#define D4       124
#define H_MLP    1024
#define B_BATCH  16384

// Scratch: MLP branch output per sample (includes b2)
__device__ float g_mlp[B_BATCH];
// Index dtype flag: 1 if xi buffer is int64 (little-endian), 0 if int32
__device__ int g_is64;

// ---------------------------------------------------------------------------
// Kernel 0: detect index dtype. If xi is int64, every odd 32-bit word of the
// first 4096 elements is 0 (values < 10000). If int32, odd words are random
// indices in [0,10000) -> P(all zero) ~ 1e-16384. Deterministic.
// ---------------------------------------------------------------------------
__global__ void detect_idx_kernel(const int* __restrict__ xi_as_i32) {
    __shared__ int any_nonzero;
    if (threadIdx.x == 0) any_nonzero = 0;
    __syncthreads();
    int acc = 0;
    for (int i = threadIdx.x; i < 4096; i += blockDim.x)
        acc |= xi_as_i32[2 * i + 1];
    if (acc) atomicOr(&any_nonzero, 1);
    __syncthreads();
    if (threadIdx.x == 0) g_is64 = (any_nonzero == 0) ? 1 : 0;
}

// ---------------------------------------------------------------------------
// Kernel 1: MLP branch. Batch-tiled so W1 (128 KB) is read ~256x total instead
// of 16384x. 64 samples per block, 256 threads: thread t owns sample s=t&63
// and j-range g=t>>6 (256 of 1024 hidden units), float4 over j. W1/b1/W2 loads
// are warp-uniform (all lanes same j, different s) -> broadcast, L1-resident.
// ---------------------------------------------------------------------------
#define MLP_BM 64
__global__ void __launch_bounds__(256) mlp_kernel(
    const float* __restrict__ xv,
    const float* __restrict__ W1,
    const float* __restrict__ b1,
    const float* __restrict__ W2,
    const float* __restrict__ b2)
{
    __shared__ float xs[MLP_BM][33];   // +1 pad: conflict-free lane access
    __shared__ float accs[MLP_BM][4];

    const int t  = threadIdx.x;
    const int b0 = blockIdx.x * MLP_BM;

    for (int i = t; i < MLP_BM * F_FIELDS; i += 256) {
        int s = i >> 5, f = i & 31;
        xs[s][f] = xv[(size_t)(b0 + s) * F_FIELDS + f];
    }
    __syncthreads();

    const int s = t & 63;
    const int g = t >> 6;

    float xr[F_FIELDS];
#pragma unroll
    for (int f = 0; f < F_FIELDS; ++f) xr[f] = xs[s][f];

    const float* w2h = W2 + D_EMB;   // rows [D, D+H) of W2 multiply the MLP part
    float acc = 0.f;
    const int jbase = g * 256;

    for (int j = jbase; j < jbase + 256; j += 4) {
        float4 dot = *(const float4*)(b1 + j);
#pragma unroll
        for (int f = 0; f < F_FIELDS; ++f) {
            float4 w = *(const float4*)(W1 + f * H_MLP + j);
            dot.x = fmaf(xr[f], w.x, dot.x);
            dot.y = fmaf(xr[f], w.y, dot.y);
            dot.z = fmaf(xr[f], w.z, dot.z);
            dot.w = fmaf(xr[f], w.w, dot.w);
        }
        float4 wo = *(const float4*)(w2h + j);
        acc = fmaf(fmaxf(dot.x, 0.f), wo.x, acc);
        acc = fmaf(fmaxf(dot.y, 0.f), wo.y, acc);
        acc = fmaf(fmaxf(dot.z, 0.f), wo.z, acc);
        acc = fmaf(fmaxf(dot.w, 0.f), wo.w, acc);
    }

    accs[s][g] = acc;
    __syncthreads();
    if (t < MLP_BM)
        g_mlp[b0 + t] = accs[t][0] + accs[t][1] + accs[t][2] + accs[t][3] + b2[0];
}

// ---------------------------------------------------------------------------
// Kernel 2: FM gather + interaction + final dot. One block per sample.
// Thread t<124 owns dims [4t,4t+4): 32 independent float4 gathers (high MLP),
// s/ss accumulated in registers, qi never materialized. 1984 B per row, rows
// are 16B-aligned (496*4 = 124*16).
// ---------------------------------------------------------------------------
__global__ void __launch_bounds__(128) fm_kernel(
    const float* __restrict__ xv,
    const void*  __restrict__ xi_raw,
    const float* __restrict__ emb,
    const float* __restrict__ W2,
    float*       __restrict__ out)
{
    __shared__ float  vx[F_FIELDS];
    __shared__ size_t off[F_FIELDS];   // row offsets in float4 units

    const int t = threadIdx.x;
    const int b = blockIdx.x;

    if (t < F_FIELDS) {
        int idx;
        if (g_is64) idx = (int)((const long long*)xi_raw)[(size_t)b * F_FIELDS + t];
        else        idx = ((const int*)xi_raw)[(size_t)b * F_FIELDS + t];
        off[t] = ((size_t)t * VOCAB + (size_t)idx) * D4;
        vx[t]  = xv[(size_t)b * F_FIELDS + t];
    }
    __syncthreads();

    float partial = 0.f;
    if (t < D4) {
        const float4* e4 = (const float4*)emb;
        float4 s  = make_float4(0.f, 0.f, 0.f, 0.f);
        float4 ss = make_float4(0.f, 0.f, 0.f, 0.f);
#pragma unroll 8
        for (int f = 0; f < F_FIELDS; ++f) {
            const float  v = vx[f];
            const float4 r = __ldg(&e4[off[f] + t]);
            float ex = r.x * v, ey = r.y * v, ez = r.z * v, ew = r.w * v;
            s.x += ex;  s.y += ey;  s.z += ez;  s.w += ew;
            ss.x = fmaf(ex, ex, ss.x);
            ss.y = fmaf(ey, ey, ss.y);
            ss.z = fmaf(ez, ez, ss.z);
            ss.w = fmaf(ew, ew, ss.w);
        }
        const float4 w = ((const float4*)W2)[t];   // first D rows of W2
        partial = 0.5f * ((s.x * s.x - ss.x) * w.x +
                          (s.y * s.y - ss.y) * w.y +
                          (s.z * s.z - ss.z) * w.z +
                          (s.w * s.w - ss.w) * w.w);
    }

    // block reduce: 4 warps
#pragma unroll
    for (int o = 16; o > 0; o >>= 1)
        partial += __shfl_down_sync(0xffffffff, partial, o);

    __shared__ float wsum[4];
    if ((t & 31) == 0) wsum[t >> 5] = partial;
    __syncthreads();
    if (t == 0)
        out[b] = wsum[0] + wsum[1] + wsum[2] + wsum[3] + g_mlp[b];
}

// ---------------------------------------------------------------------------
extern "C" void kernel_launch(void* const* d_in, const int* in_sizes, int n_in,
                              void* d_out, int out_size)
{
    const float* xv  = (const float*)d_in[0];
    const void*  xi  = d_in[1];
    const float* emb = (const float*)d_in[2];
    const float* W1  = (const float*)d_in[3];
    const float* b1  = (const float*)d_in[4];
    const float* W2  = (const float*)d_in[5];
    const float* b2  = (const float*)d_in[6];
    float* out = (float*)d_out;

    detect_idx_kernel<<<1, 256>>>((const int*)xi);
    mlp_kernel<<<B_BATCH / MLP_BM, 256>>>(xv, W1, b1, W2, b2);
    fm_kernel<<<B_BATCH, 128>>>(xv, xi, emb, W2, out);
}

// round 3
// speedup vs baseline: 1.4743x; 1.4743x over previous
#include <cuda_runtime.h>
#include <cuda_bf16.h>
#include <cstdint>

// Problem constants
#define F_FIELDS 32
#define VOCAB    10000
#define D_EMB    496          // = 124 float4
#define D4       124
#define H_MLP    1024
#define B_BATCH  16384

#define MLP_BM      64                      // samples per MLP block
#define MLP_BLOCKS  (B_BATCH / MLP_BM)      // 256
#define FM_SPB      2                       // samples per FM block (256 threads)
#define FM_BLOCKS   (B_BATCH / FM_SPB)      // 8192

// Scratch: MLP branch output per sample (includes b2)
__device__ float g_mlp[B_BATCH];

// ---------------------------------------------------------------------------
// Mixed kernel: blocks [0, MLP_BLOCKS) run the FMA-bound MLP role; blocks
// [MLP_BLOCKS, MLP_BLOCKS+FM_BLOCKS) run the DRAM-bound FM gather role.
// The two roles overlap on the SMs, hiding MLP compute under the gather.
// ---------------------------------------------------------------------------
__global__ void __launch_bounds__(256) mixed_kernel(
    const float* __restrict__ xv,
    const void*  __restrict__ xi_raw,
    const float* __restrict__ emb,
    const float* __restrict__ W1,
    const float* __restrict__ b1,
    const float* __restrict__ W2,
    const float* __restrict__ b2,
    float*       __restrict__ out)
{
    const int t = threadIdx.x;

    if (blockIdx.x < MLP_BLOCKS) {
        // ----------------- MLP role -----------------
        // 64 samples/block, 256 threads: thread owns sample s=t&63, hidden
        // range g=t>>6 (256 of 1024 units), float4 over j. W1/b1/W2 loads are
        // warp-uniform -> broadcast, L1/L2 resident (W1 read 256x, not 16384x).
        __shared__ float xs[MLP_BM][33];
        __shared__ float accs[MLP_BM][4];

        const int b0 = blockIdx.x * MLP_BM;

        for (int i = t; i < MLP_BM * F_FIELDS; i += 256) {
            int s = i >> 5, f = i & 31;
            xs[s][f] = xv[(size_t)(b0 + s) * F_FIELDS + f];
        }
        __syncthreads();

        const int s = t & 63;
        const int g = t >> 6;

        float xr[F_FIELDS];
#pragma unroll
        for (int f = 0; f < F_FIELDS; ++f) xr[f] = xs[s][f];

        const float* w2h = W2 + D_EMB;   // rows [D, D+H) of W2
        float acc = 0.f;
        const int jbase = g * 256;

        for (int j = jbase; j < jbase + 256; j += 4) {
            float4 dot = *(const float4*)(b1 + j);
#pragma unroll
            for (int f = 0; f < F_FIELDS; ++f) {
                float4 w = *(const float4*)(W1 + f * H_MLP + j);
                dot.x = fmaf(xr[f], w.x, dot.x);
                dot.y = fmaf(xr[f], w.y, dot.y);
                dot.z = fmaf(xr[f], w.z, dot.z);
                dot.w = fmaf(xr[f], w.w, dot.w);
            }
            float4 wo = *(const float4*)(w2h + j);
            acc = fmaf(fmaxf(dot.x, 0.f), wo.x, acc);
            acc = fmaf(fmaxf(dot.y, 0.f), wo.y, acc);
            acc = fmaf(fmaxf(dot.z, 0.f), wo.z, acc);
            acc = fmaf(fmaxf(dot.w, 0.f), wo.w, acc);
        }

        accs[s][g] = acc;
        __syncthreads();
        if (t < MLP_BM)
            g_mlp[b0 + t] = accs[t][0] + accs[t][1] + accs[t][2] + accs[t][3] + b2[0];

    } else {
        // ----------------- FM gather role -----------------
        // 2 samples per 256-thread block. Thread tt<124 of each half owns dims
        // [4tt,4tt+4): 32 independent float4 gathers, unroll 16 for deep MLP.
        __shared__ const float4* basep[FM_SPB][F_FIELDS];
        __shared__ float vx[FM_SPB][F_FIELDS];
        __shared__ int   is64_s;
        __shared__ float wsum[FM_SPB][4];

        const int b0 = (blockIdx.x - MLP_BLOCKS) * FM_SPB;

        // Inline index-dtype detection from the first 256B of xi: if the
        // buffer is int64 (values < 10000), every odd 32-bit word is 0.
        // For int32 random indices, P(32 odd words all zero) ~ 1e-128.
        if (t < 32) {
            int v = ((const int*)xi_raw)[2 * t + 1];
            unsigned nz = __ballot_sync(0xffffffff, v != 0);
            if (t == 0) is64_s = (nz == 0) ? 1 : 0;
        }
        __syncthreads();

        if (t < FM_SPB * F_FIELDS) {
            const int sub = t >> 5, f = t & 31;
            const int b = b0 + sub;
            int idx;
            if (is64_s) idx = (int)((const long long*)xi_raw)[(size_t)b * F_FIELDS + f];
            else        idx = ((const int*)xi_raw)[(size_t)b * F_FIELDS + f];
            basep[sub][f] = (const float4*)emb + ((size_t)f * VOCAB + (size_t)idx) * D4;
            vx[sub][f] = xv[(size_t)b * F_FIELDS + f];
        }
        __syncthreads();

        const int sub = t >> 7;       // which sample half
        const int tt  = t & 127;

        float partial = 0.f;
        if (tt < D4) {
            float4 s4 = make_float4(0.f, 0.f, 0.f, 0.f);
            float4 ss = make_float4(0.f, 0.f, 0.f, 0.f);
#pragma unroll 16
            for (int f = 0; f < F_FIELDS; ++f) {
                const float  v = vx[sub][f];
                const float4 r = __ldg(basep[sub][f] + tt);
                float ex = r.x * v, ey = r.y * v, ez = r.z * v, ew = r.w * v;
                s4.x += ex;  s4.y += ey;  s4.z += ez;  s4.w += ew;
                ss.x = fmaf(ex, ex, ss.x);
                ss.y = fmaf(ey, ey, ss.y);
                ss.z = fmaf(ez, ez, ss.z);
                ss.w = fmaf(ew, ew, ss.w);
            }
            const float4 w = ((const float4*)W2)[tt];  // first D rows of W2
            partial = 0.5f * ((s4.x * s4.x - ss.x) * w.x +
                              (s4.y * s4.y - ss.y) * w.y +
                              (s4.z * s4.z - ss.z) * w.z +
                              (s4.w * s4.w - ss.w) * w.w);
        }

        // reduce within each 128-thread half (4 warps)
#pragma unroll
        for (int o = 16; o > 0; o >>= 1)
            partial += __shfl_down_sync(0xffffffff, partial, o);

        if ((tt & 31) == 0) wsum[sub][tt >> 5] = partial;
        __syncthreads();
        if (tt == 0)
            out[b0 + sub] = wsum[sub][0] + wsum[sub][1] + wsum[sub][2] + wsum[sub][3];
    }
}

// ---------------------------------------------------------------------------
// Combine: out[b] += g_mlp[b]. Tiny (16384 elements).
// ---------------------------------------------------------------------------
__global__ void __launch_bounds__(256) add_kernel(float* __restrict__ out)
{
    int i = blockIdx.x * 256 + threadIdx.x;
    if (i < B_BATCH) out[i] += g_mlp[i];
}

// ---------------------------------------------------------------------------
extern "C" void kernel_launch(void* const* d_in, const int* in_sizes, int n_in,
                              void* d_out, int out_size)
{
    const float* xv  = (const float*)d_in[0];
    const void*  xi  = d_in[1];
    const float* emb = (const float*)d_in[2];
    const float* W1  = (const float*)d_in[3];
    const float* b1  = (const float*)d_in[4];
    const float* W2  = (const float*)d_in[5];
    const float* b2  = (const float*)d_in[6];
    float* out = (float*)d_out;

    mixed_kernel<<<MLP_BLOCKS + FM_BLOCKS, 256>>>(xv, xi, emb, W1, b1, W2, b2, out);
    add_kernel<<<(B_BATCH + 255) / 256, 256>>>(out);
}